// round 2
// baseline (speedup 1.0000x reference)
#include <cuda_runtime.h>

// NetVLAD: B=64, C=128, K=64, N=4096
#define NV_B 64
#define NV_C 128
#define NV_K 64
#define NV_N 4096
#define NV_TN 64         // n-tile per inner iteration
#define NV_SPLIT 16      // CTAs per batch
#define NV_TILES 4       // tiles per CTA (64 tiles / 16 splits)

#define XS_PITCH 68      // padded row (floats) for the x tile
#define LT_PITCH 68      // padded row (floats) for logits/softmax tile
#define SMEM_A_BYTES ((NV_C*NV_K + NV_C*XS_PITCH + NV_TN*LT_PITCH) * 4)

// scratch: partial vlad sums + partial a-sums, indexed by blockIdx (= b*16+s)
__device__ float g_pvlad[(size_t)NV_B * NV_SPLIT * NV_K * NV_C]; // 32 MB
__device__ float g_pasum[NV_B * NV_SPLIT * NV_K];

typedef unsigned long long u64;

__device__ __forceinline__ u64 pack2(float x){
    u64 r; asm("mov.b64 %0,{%1,%1};" : "=l"(r) : "f"(x)); return r;
}
__device__ __forceinline__ u64 packab(float a, float b){
    u64 r; asm("mov.b64 %0,{%1,%2};" : "=l"(r) : "f"(a), "f"(b)); return r;
}
__device__ __forceinline__ void ffma2(u64 &d, u64 a, u64 b){
    asm("fma.rn.f32x2 %0,%1,%2,%0;" : "+l"(d) : "l"(a), "l"(b));
}
__device__ __forceinline__ float2 unpack2(u64 v){
    float2 r; asm("mov.b64 {%0,%1},%2;" : "=f"(r.x), "=f"(r.y) : "l"(v)); return r;
}

// ---------------------------------------------------------------------------
// Kernel A: per (batch, n-split): logits GEMM -> softmax -> vlad-partial GEMM
// ---------------------------------------------------------------------------
__global__ __launch_bounds__(256, 2)
void netvlad_main(const float* __restrict__ x, const float* __restrict__ conv_w)
{
    extern __shared__ float sm[];
    float* Ws = sm;                        // [C][K]  = conv_w transposed
    float* Xs = sm + NV_C * NV_K;          // [C][XS_PITCH] x tile (n contiguous)
    float* Lt = Xs + NV_C * XS_PITCH;      // [TN][LT_PITCH] logits, n-major

    const int tid = threadIdx.x;
    const int b   = blockIdx.x >> 4;
    const int s   = blockIdx.x & 15;

    // load conv_w transposed into smem (once per CTA; ordered by first sync)
    for (int i = tid; i < NV_K * NV_C; i += 256) {
        int k = i >> 7, c = i & 127;
        Ws[c * NV_K + k] = conv_w[i];
    }

    const int lty = tid >> 4, ltx = tid & 15;   // 16x16 thread grid
    const int g1k0 = lty * 4, g1n0 = ltx * 4;   // GEMM1: 4k x 4n per thread

    // GEMM2 accumulators: acc[i][j] ~ (k = 4*lty+i, c = ltx + 16*j), paired over n
    u64 acc[4][8];
    #pragma unroll
    for (int i = 0; i < 4; i++)
        #pragma unroll
        for (int j = 0; j < 8; j++) acc[i][j] = 0ULL;
    float asum0 = 0.f, asum1 = 0.f, asum2 = 0.f, asum3 = 0.f;

    const float* xb = x + (size_t)b * NV_C * NV_N;

    for (int tt = 0; tt < NV_TILES; tt++) {
        const int n0g = (s * NV_TILES + tt) * NV_TN;
        __syncthreads();   // previous GEMM2 done (and Ws ready on iter 0)

        // ---- load x tile: Xs[c][n] (rows padded to 68 floats) ----
        #pragma unroll
        for (int r = 0; r < 8; r++) {
            int q = tid + 256 * r;
            int c = q >> 4, nq = q & 15;
            float4 v = *(const float4*)(xb + (size_t)c * NV_N + n0g + 4 * nq);
            *(float4*)(Xs + c * XS_PITCH + 4 * nq) = v;
        }
        __syncthreads();

        // ---- GEMM1: L[k][n] = sum_c W[k][c] * x[c][n], f32x2-packed over n ----
        {
            u64 la[4][2];
            #pragma unroll
            for (int i = 0; i < 4; i++) { la[i][0] = 0ULL; la[i][1] = 0ULL; }
            #pragma unroll 4
            for (int c = 0; c < NV_C; c++) {
                float4 wv = *(const float4*)(Ws + c * NV_K + g1k0);
                float4 xv = *(const float4*)(Xs + c * XS_PITCH + g1n0);
                u64 xp0 = packab(xv.x, xv.y);
                u64 xp1 = packab(xv.z, xv.w);
                u64 w0 = pack2(wv.x), w1 = pack2(wv.y), w2 = pack2(wv.z), w3 = pack2(wv.w);
                ffma2(la[0][0], w0, xp0); ffma2(la[0][1], w0, xp1);
                ffma2(la[1][0], w1, xp0); ffma2(la[1][1], w1, xp1);
                ffma2(la[2][0], w2, xp0); ffma2(la[2][1], w2, xp1);
                ffma2(la[3][0], w3, xp0); ffma2(la[3][1], w3, xp1);
            }
            // store transposed: Lt[n][k]
            float l[4][4];
            #pragma unroll
            for (int i = 0; i < 4; i++) {
                float2 p0 = unpack2(la[i][0]);
                float2 p1 = unpack2(la[i][1]);
                l[i][0] = p0.x; l[i][1] = p0.y; l[i][2] = p1.x; l[i][3] = p1.y;
            }
            #pragma unroll
            for (int j = 0; j < 4; j++)
                *(float4*)(Lt + (g1n0 + j) * LT_PITCH + g1k0) =
                    make_float4(l[0][j], l[1][j], l[2][j], l[3][j]);
        }
        __syncthreads();

        // ---- softmax over k (row of Lt), 2 threads per n-row ----
        if (tid < 128) {
            int n = tid >> 1, h = tid & 1;
            float* row = Lt + n * LT_PITCH + h * 32;
            float4 v[8];
            float m = -1e30f;
            #pragma unroll
            for (int i2 = 0; i2 < 8; i2++) {
                v[i2] = *(float4*)(row + 4 * i2);
                m = fmaxf(m, fmaxf(fmaxf(v[i2].x, v[i2].y), fmaxf(v[i2].z, v[i2].w)));
            }
            m = fmaxf(m, __shfl_xor_sync(0xffffffffu, m, 1));
            float ss = 0.f;
            #pragma unroll
            for (int i2 = 0; i2 < 8; i2++) {
                v[i2].x = __expf(v[i2].x - m);
                v[i2].y = __expf(v[i2].y - m);
                v[i2].z = __expf(v[i2].z - m);
                v[i2].w = __expf(v[i2].w - m);
                ss += (v[i2].x + v[i2].y) + (v[i2].z + v[i2].w);
            }
            ss += __shfl_xor_sync(0xffffffffu, ss, 1);
            float inv = 1.0f / ss;
            #pragma unroll
            for (int i2 = 0; i2 < 8; i2++) {
                v[i2].x *= inv; v[i2].y *= inv; v[i2].z *= inv; v[i2].w *= inv;
                *(float4*)(row + 4 * i2) = v[i2];
            }
        }
        __syncthreads();

        // ---- GEMM2: acc[k][c] += sum_n a[k][n]*x[c][n], f32x2-paired over n ----
        #pragma unroll 2
        for (int nc = 0; nc < 32; nc++) {
            float4 a0 = *(const float4*)(Lt + (2 * nc + 0) * LT_PITCH + g1k0);
            float4 a1 = *(const float4*)(Lt + (2 * nc + 1) * LT_PITCH + g1k0);
            u64 ap0 = packab(a0.x, a1.x);
            u64 ap1 = packab(a0.y, a1.y);
            u64 ap2 = packab(a0.z, a1.z);
            u64 ap3 = packab(a0.w, a1.w);
            if (ltx == 0) {   // a-column sums (each k owned by exactly one thread)
                asum0 += a0.x + a1.x;
                asum1 += a0.y + a1.y;
                asum2 += a0.z + a1.z;
                asum3 += a0.w + a1.w;
            }
            #pragma unroll
            for (int j = 0; j < 8; j++) {
                u64 xp = *(const u64*)(Xs + (ltx + 16 * j) * XS_PITCH + 2 * nc);
                ffma2(acc[0][j], ap0, xp);
                ffma2(acc[1][j], ap1, xp);
                ffma2(acc[2][j], ap2, xp);
                ffma2(acc[3][j], ap3, xp);
            }
        }
    }

    // ---- write partials (each (k,c) owned by exactly one thread) ----
    float* pv = g_pvlad + (size_t)blockIdx.x * (NV_K * NV_C);
    #pragma unroll
    for (int i = 0; i < 4; i++)
        #pragma unroll
        for (int j = 0; j < 8; j++) {
            float2 p = unpack2(acc[i][j]);
            pv[(g1k0 + i) * NV_C + ltx + 16 * j] = p.x + p.y;
        }
    if (ltx == 0) {
        float* pa = g_pasum + blockIdx.x * NV_K + g1k0;
        pa[0] = asum0; pa[1] = asum1; pa[2] = asum2; pa[3] = asum3;
    }
}

// ---------------------------------------------------------------------------
// Kernel B: reduce splits, subtract asum*centroid, intra + global L2 normalize
// ---------------------------------------------------------------------------
__global__ __launch_bounds__(256)
void netvlad_finalize(const float* __restrict__ centroids, float* __restrict__ out)
{
    __shared__ float vbuf[NV_K * NV_C];
    __shared__ float wpart[NV_K][4];
    __shared__ float asumt[NV_K];
    __shared__ float invrow[NV_K];
    __shared__ float g2[2];

    const int b = blockIdx.x, t = threadIdx.x;
    const int w = t >> 5, lane = t & 31;

    if (t < NV_K) {
        float sum = 0.f;
        #pragma unroll
        for (int sp = 0; sp < NV_SPLIT; sp++)
            sum += g_pasum[(b * NV_SPLIT + sp) * NV_K + t];
        asumt[t] = sum;
    }
    __syncthreads();

    const size_t base = (size_t)b * NV_SPLIT * (NV_K * NV_C);
    for (int i = 0; i < 32; i++) {
        int flat = i * 256 + t;
        int k = flat >> 7;
        float v = 0.f;
        #pragma unroll
        for (int sp = 0; sp < NV_SPLIT; sp++)
            v += g_pvlad[base + (size_t)sp * (NV_K * NV_C) + flat];
        v -= asumt[k] * centroids[flat];
        vbuf[flat] = v;
        float v2 = v * v;
        #pragma unroll
        for (int o = 16; o > 0; o >>= 1)
            v2 += __shfl_xor_sync(0xffffffffu, v2, o);
        // each warp covers 32 elements of one k-row; each k hit by exactly 4 warps total
        if (lane == 0) wpart[k][w & 3] = v2;
    }
    __syncthreads();

    if (t < NV_K) {
        float rs  = wpart[t][0] + wpart[t][1] + wpart[t][2] + wpart[t][3];
        float rn  = sqrtf(rs);
        float inv = 1.0f / fmaxf(rn, 1e-12f);
        invrow[t] = inv;
        float c1 = rn * inv;          // == 1 when rn >= eps (matches reference)
        float contrib = c1 * c1;
        #pragma unroll
        for (int o = 16; o > 0; o >>= 1)
            contrib += __shfl_xor_sync(0xffffffffu, contrib, o);
        if (lane == 0) g2[w] = contrib;
    }
    __syncthreads();

    const float ginv = 1.0f / fmaxf(sqrtf(g2[0] + g2[1]), 1e-12f);
    float* ob = out + (size_t)b * (NV_K * NV_C);
    for (int i = 0; i < 32; i++) {
        int flat = i * 256 + t;
        ob[flat] = vbuf[flat] * invrow[flat >> 7] * ginv;
    }
}

// ---------------------------------------------------------------------------
extern "C" void kernel_launch(void* const* d_in, const int* in_sizes, int n_in,
                              void* d_out, int out_size)
{
    const float* x         = (const float*)d_in[0];
    const float* conv_w    = (const float*)d_in[1];
    const float* centroids = (const float*)d_in[2];
    float* out = (float*)d_out;

    cudaFuncSetAttribute(netvlad_main,
                         cudaFuncAttributeMaxDynamicSharedMemorySize, SMEM_A_BYTES);
    netvlad_main<<<NV_B * NV_SPLIT, 256, SMEM_A_BYTES>>>(x, conv_w);
    netvlad_finalize<<<NV_B, 256>>>(centroids, out);
}

// round 4
// speedup vs baseline: 2.2631x; 2.2631x over previous
#include <cuda_runtime.h>
#include <cuda_bf16.h>
#include <cstdint>

// NetVLAD: B=64, C=128, K=64, N=4096 — mma.sync bf16 3-term split
#define NV_B 64
#define NV_C 128
#define NV_K 64
#define NV_N 4096
#define NV_SPLIT 8
#define NV_TILES 4

// smem pitches (bf16 elements)
#define PX 136      // Xn rows (c): 128 + 8 pad  -> 272 B (rows shift 16B mod 128)
#define PW 136      // W rows (k)
#define PA 72       // At rows (n): 64 + 8 pad   -> 144 B

// smem byte offsets
#define XN_HI 0
#define XN_LO (XN_HI + 128 * PX * 2)      // 34816
#define W_HI  (XN_LO + 128 * PX * 2)      // 69632
#define W_LO  (W_HI + 64 * PW * 2)        // 87040
#define AT_HI (W_LO + 64 * PW * 2)        // 104448
#define AT_LO (AT_HI + 128 * PA * 2)      // 122880
#define ASUM_B (AT_LO + 128 * PA * 2)     // 141312
#define SMEM_TOTAL (ASUM_B + 8 * 64 * 4)  // 143360

// scratch partials
__device__ float g_pvlad[(size_t)NV_B * NV_SPLIT * NV_K * NV_C];  // 16 MB
__device__ float g_pasum[NV_B * NV_SPLIT * NV_K];

__device__ __forceinline__ uint32_t smem_u32(const void* p) {
    uint32_t a;
    asm("{ .reg .u64 t; cvta.to.shared.u64 t, %1; cvt.u32.u64 %0, t; }" : "=r"(a) : "l"(p));
    return a;
}
__device__ __forceinline__ void ldmx4(uint32_t* r, uint32_t a) {
    asm volatile("ldmatrix.sync.aligned.m8n8.x4.shared.b16 {%0,%1,%2,%3},[%4];"
        : "=r"(r[0]), "=r"(r[1]), "=r"(r[2]), "=r"(r[3]) : "r"(a));
}
__device__ __forceinline__ void ldmx4t(uint32_t* r, uint32_t a) {
    asm volatile("ldmatrix.sync.aligned.m8n8.x4.trans.shared.b16 {%0,%1,%2,%3},[%4];"
        : "=r"(r[0]), "=r"(r[1]), "=r"(r[2]), "=r"(r[3]) : "r"(a));
}
__device__ __forceinline__ void mma16816(float* d, const uint32_t* a, const uint32_t* b) {
    asm volatile("mma.sync.aligned.m16n8k16.row.col.f32.bf16.bf16.f32 "
        "{%0,%1,%2,%3},{%4,%5,%6,%7},{%8,%9},{%0,%1,%2,%3};"
        : "+f"(d[0]), "+f"(d[1]), "+f"(d[2]), "+f"(d[3])
        : "r"(a[0]), "r"(a[1]), "r"(a[2]), "r"(a[3]), "r"(b[0]), "r"(b[1]));
}

// ---------------------------------------------------------------------------
__global__ __launch_bounds__(256, 1)
void netvlad_mma(const float* __restrict__ x, const float* __restrict__ conv_w)
{
    extern __shared__ char smc[];
    const uint32_t sb = smem_u32(smc);
    const int tid  = threadIdx.x;
    const int w    = tid >> 5;
    const int lane = tid & 31;
    const int g    = lane >> 2;      // group id (row within fragment)
    const int t4   = lane & 3;       // thread-in-group (col pair)
    const int q    = lane >> 3;      // ldmatrix quadrant
    const int qi   = lane & 7;
    const int b    = blockIdx.x >> 3;
    const int s    = blockIdx.x & 7;

    // ---- W -> smem hi/lo (native [k][c] layout, padded pitch) ----
    {
        int k = tid >> 2, c0 = (tid & 3) * 32;
        const float* wr = conv_w + k * NV_C + c0;
        char* wh = smc + W_HI + k * (PW * 2) + c0 * 2;
        char* wl = smc + W_LO + k * (PW * 2) + c0 * 2;
        #pragma unroll
        for (int e = 0; e < 8; e++) {
            float4 v = *(const float4*)(wr + 4 * e);
            __nv_bfloat16 h0 = __float2bfloat16(v.x), h1 = __float2bfloat16(v.y);
            __nv_bfloat16 h2 = __float2bfloat16(v.z), h3 = __float2bfloat16(v.w);
            float l0 = v.x - __bfloat162float(h0), l1 = v.y - __bfloat162float(h1);
            float l2 = v.z - __bfloat162float(h2), l3 = v.w - __bfloat162float(h3);
            *(__nv_bfloat162*)(wh + 8 * e)     = __nv_bfloat162(h0, h1);
            *(__nv_bfloat162*)(wh + 8 * e + 4) = __nv_bfloat162(h2, h3);
            *(__nv_bfloat162*)(wl + 8 * e)     = __nv_bfloat162(__float2bfloat16(l0), __float2bfloat16(l1));
            *(__nv_bfloat162*)(wl + 8 * e + 4) = __nv_bfloat162(__float2bfloat16(l2), __float2bfloat16(l3));
        }
    }

    // ---- per-lane ldmatrix base addresses ----
    // GEMM1 A (trans on Xn): S-row = cs*16 + (q>>1)*8 + qi, S-col = 16w + (q&1)*8
    const uint32_t a1b = sb + XN_HI + (uint32_t)(((q >> 1) * 8 + qi) * (PX * 2))
                       + (uint32_t)((16 * w + (q & 1) * 8) * 2);
    // GEMM1 B (W, hi/lo combined): row = kt*8 + qi, col = cs*16 + (q&1)*8; q>=2 -> lo
    const uint32_t b1b = sb + ((q & 2) ? W_LO : W_HI)
                       + (uint32_t)(qi * (PW * 2)) + (uint32_t)((q & 1) * 16);
    // GEMM2 A (Xn non-trans): row = 16w + (q&1)*8 + qi, col = ns*16 + (q>>1)*8
    const uint32_t a2b = sb + XN_HI + (uint32_t)((16 * w + (q & 1) * 8 + qi) * (PX * 2))
                       + (uint32_t)(((q >> 1) * 8) * 2);
    // GEMM2 B (At trans, hi/lo combined): row = ns*16 + (q&1)*8 + qi, col = kt*8
    const uint32_t b2b = sb + ((q & 2) ? AT_LO : AT_HI)
                       + (uint32_t)(((q & 1) * 8 + qi) * (PA * 2));

    float d2[8][4];
    float asum[8][2];
    #pragma unroll
    for (int kt = 0; kt < 8; kt++) {
        d2[kt][0] = d2[kt][1] = d2[kt][2] = d2[kt][3] = 0.f;
        asum[kt][0] = asum[kt][1] = 0.f;
    }

    const float* xb = x + (size_t)b * NV_C * NV_N + s * 512;

    for (int tt = 0; tt < NV_TILES; tt++) {
        // ---- convert x tile -> Xn hi/lo [c][n] ----
        {
            int cc = tid >> 1, nh = (tid & 1) * 64;
            const float* xr = xb + (size_t)cc * NV_N + tt * 128 + nh;
            char* xnh = smc + XN_HI + cc * (PX * 2) + nh * 2;
            char* xnl = smc + XN_LO + cc * (PX * 2) + nh * 2;
            #pragma unroll
            for (int j = 0; j < 16; j++) {
                float4 v = *(const float4*)(xr + 4 * j);
                __nv_bfloat16 h0 = __float2bfloat16(v.x), h1 = __float2bfloat16(v.y);
                __nv_bfloat16 h2 = __float2bfloat16(v.z), h3 = __float2bfloat16(v.w);
                float l0 = v.x - __bfloat162float(h0), l1 = v.y - __bfloat162float(h1);
                float l2 = v.z - __bfloat162float(h2), l3 = v.w - __bfloat162float(h3);
                *(__nv_bfloat162*)(xnh + 8 * j)     = __nv_bfloat162(h0, h1);
                *(__nv_bfloat162*)(xnh + 8 * j + 4) = __nv_bfloat162(h2, h3);
                *(__nv_bfloat162*)(xnl + 8 * j)     = __nv_bfloat162(__float2bfloat16(l0), __float2bfloat16(l1));
                *(__nv_bfloat162*)(xnl + 8 * j + 4) = __nv_bfloat162(__float2bfloat16(l2), __float2bfloat16(l3));
            }
        }
        __syncthreads();

        // ---- GEMM1: L[n(16w..+16)][k(64)] = Xt @ W^T, 3-term split ----
        float d1[8][4];
        #pragma unroll
        for (int kt = 0; kt < 8; kt++)
            d1[kt][0] = d1[kt][1] = d1[kt][2] = d1[kt][3] = 0.f;

        #pragma unroll
        for (int cs = 0; cs < 8; cs++) {
            uint32_t ah[4], al[4];
            ldmx4t(ah, a1b + cs * 16 * (PX * 2));
            ldmx4t(al, a1b + cs * 16 * (PX * 2) + (XN_LO - XN_HI));
            #pragma unroll
            for (int kt = 0; kt < 8; kt++) {
                uint32_t bb[4];
                ldmx4(bb, b1b + kt * (8 * PW * 2) + cs * 32);
                mma16816(d1[kt], ah, bb);       // Ah*Bh
                mma16816(d1[kt], ah, bb + 2);   // Ah*Bl
                mma16816(d1[kt], al, bb);       // Al*Bh
            }
        }

        // ---- softmax over k, fully in registers (rows n=16w+g and 16w+8+g) ----
        {
            float m0 = -1e30f, m1 = -1e30f;
            #pragma unroll
            for (int kt = 0; kt < 8; kt++) {
                m0 = fmaxf(m0, fmaxf(d1[kt][0], d1[kt][1]));
                m1 = fmaxf(m1, fmaxf(d1[kt][2], d1[kt][3]));
            }
            m0 = fmaxf(m0, __shfl_xor_sync(0xffffffffu, m0, 1));
            m0 = fmaxf(m0, __shfl_xor_sync(0xffffffffu, m0, 2));
            m1 = fmaxf(m1, __shfl_xor_sync(0xffffffffu, m1, 1));
            m1 = fmaxf(m1, __shfl_xor_sync(0xffffffffu, m1, 2));
            float s0 = 0.f, s1 = 0.f;
            #pragma unroll
            for (int kt = 0; kt < 8; kt++) {
                d1[kt][0] = __expf(d1[kt][0] - m0); s0 += d1[kt][0];
                d1[kt][1] = __expf(d1[kt][1] - m0); s0 += d1[kt][1];
                d1[kt][2] = __expf(d1[kt][2] - m1); s1 += d1[kt][2];
                d1[kt][3] = __expf(d1[kt][3] - m1); s1 += d1[kt][3];
            }
            s0 += __shfl_xor_sync(0xffffffffu, s0, 1);
            s0 += __shfl_xor_sync(0xffffffffu, s0, 2);
            s1 += __shfl_xor_sync(0xffffffffu, s1, 1);
            s1 += __shfl_xor_sync(0xffffffffu, s1, 2);
            float inv0 = 1.0f / s0, inv1 = 1.0f / s1;

            char* r0h = smc + AT_HI + (16 * w + g) * (PA * 2) + (2 * t4) * 2;
            char* r1h = r0h + 8 * (PA * 2);
            #pragma unroll
            for (int kt = 0; kt < 8; kt++) {
                float a00 = d1[kt][0] * inv0, a01 = d1[kt][1] * inv0;
                float a10 = d1[kt][2] * inv1, a11 = d1[kt][3] * inv1;
                asum[kt][0] += a00 + a10;
                asum[kt][1] += a01 + a11;
                __nv_bfloat16 h00 = __float2bfloat16(a00), h01 = __float2bfloat16(a01);
                __nv_bfloat16 h10 = __float2bfloat16(a10), h11 = __float2bfloat16(a11);
                float e00 = a00 - __bfloat162float(h00), e01 = a01 - __bfloat162float(h01);
                float e10 = a10 - __bfloat162float(h10), e11 = a11 - __bfloat162float(h11);
                *(__nv_bfloat162*)(r0h + kt * 16) = __nv_bfloat162(h00, h01);
                *(__nv_bfloat162*)(r1h + kt * 16) = __nv_bfloat162(h10, h11);
                *(__nv_bfloat162*)(r0h + kt * 16 + (AT_LO - AT_HI)) =
                    __nv_bfloat162(__float2bfloat16(e00), __float2bfloat16(e01));
                *(__nv_bfloat162*)(r1h + kt * 16 + (AT_LO - AT_HI)) =
                    __nv_bfloat162(__float2bfloat16(e10), __float2bfloat16(e11));
            }
        }
        __syncthreads();

        // ---- GEMM2: V[c(16w..+16)][k(64)] += Xn @ At^T, 3-term split ----
        #pragma unroll
        for (int ns = 0; ns < 8; ns++) {
            uint32_t ah[4], al[4];
            ldmx4(ah, a2b + ns * 32);
            ldmx4(al, a2b + ns * 32 + (XN_LO - XN_HI));
            #pragma unroll
            for (int kt = 0; kt < 8; kt++) {
                uint32_t bb[4];
                ldmx4t(bb, b2b + ns * 16 * (PA * 2) + kt * 16);
                mma16816(d2[kt], ah, bb);       // Xh*Ah
                mma16816(d2[kt], ah, bb + 2);   // Xh*Al
                mma16816(d2[kt], al, bb);       // Xl*Ah
            }
        }
        __syncthreads();   // smem free for next tile's conversion
    }

    // ---- drain D2 -> g_pvlad ----
    {
        float* pv = g_pvlad + (size_t)blockIdx.x * (NV_K * NV_C);
        const int c0 = 16 * w + g;
        #pragma unroll
        for (int kt = 0; kt < 8; kt++) {
            int k0 = kt * 8 + 2 * t4;
            pv[k0 * NV_C + c0]             = d2[kt][0];
            pv[(k0 + 1) * NV_C + c0]       = d2[kt][1];
            pv[k0 * NV_C + c0 + 8]         = d2[kt][2];
            pv[(k0 + 1) * NV_C + c0 + 8]   = d2[kt][3];
        }
    }

    // ---- asum: reduce over g (xor 4,8,16), stash per warp, then over warps ----
    float* asum_buf = (float*)(smc + ASUM_B);
    #pragma unroll
    for (int kt = 0; kt < 8; kt++) {
        #pragma unroll
        for (int j = 0; j < 2; j++) {
            float v = asum[kt][j];
            v += __shfl_xor_sync(0xffffffffu, v, 4);
            v += __shfl_xor_sync(0xffffffffu, v, 8);
            v += __shfl_xor_sync(0xffffffffu, v, 16);
            asum[kt][j] = v;
        }
    }
    if (lane < 4) {
        #pragma unroll
        for (int kt = 0; kt < 8; kt++) {
            asum_buf[w * 64 + kt * 8 + 2 * t4]     = asum[kt][0];
            asum_buf[w * 64 + kt * 8 + 2 * t4 + 1] = asum[kt][1];
        }
    }
    __syncthreads();
    if (tid < 64) {
        float ssum = 0.f;
        #pragma unroll
        for (int ww = 0; ww < 8; ww++) ssum += asum_buf[ww * 64 + tid];
        g_pasum[blockIdx.x * NV_K + tid] = ssum;
    }
}

// ---------------------------------------------------------------------------
// finalize: reduce splits, subtract asum*centroid, intra + global L2 normalize
// ---------------------------------------------------------------------------
__global__ __launch_bounds__(1024)
void netvlad_finalize(const float* __restrict__ centroids, float* __restrict__ out)
{
    __shared__ float vbuf[NV_K * NV_C];
    __shared__ float wpart[NV_K][4];
    __shared__ float asumt[NV_K];
    __shared__ float invrow[NV_K];
    __shared__ float g2[2];

    const int b = blockIdx.x, t = threadIdx.x;
    const int w = t >> 5, lane = t & 31;

    if (t < NV_K) {
        float sum = 0.f;
        #pragma unroll
        for (int sp = 0; sp < NV_SPLIT; sp++)
            sum += g_pasum[(b * NV_SPLIT + sp) * NV_K + t];
        asumt[t] = sum;
    }
    __syncthreads();

    const size_t base = (size_t)b * NV_SPLIT * (NV_K * NV_C);
    #pragma unroll
    for (int i = 0; i < 8; i++) {
        int flat = i * 1024 + t;
        int k = flat >> 7;
        float v = 0.f;
        #pragma unroll
        for (int sp = 0; sp < NV_SPLIT; sp++)
            v += g_pvlad[base + (size_t)sp * (NV_K * NV_C) + flat];
        v -= asumt[k] * centroids[flat];
        vbuf[flat] = v;
        float v2 = v * v;
        #pragma unroll
        for (int o = 16; o > 0; o >>= 1)
            v2 += __shfl_xor_sync(0xffffffffu, v2, o);
        if (lane == 0) wpart[k][w & 3] = v2;
    }
    __syncthreads();

    if (t < NV_K) {
        float rs  = wpart[t][0] + wpart[t][1] + wpart[t][2] + wpart[t][3];
        float rn  = sqrtf(rs);
        float inv = 1.0f / fmaxf(rn, 1e-12f);
        invrow[t] = inv;
        float c1 = rn * inv;
        float contrib = c1 * c1;
        #pragma unroll
        for (int o = 16; o > 0; o >>= 1)
            contrib += __shfl_xor_sync(0xffffffffu, contrib, o);
        if (lane == 0) g2[w] = contrib;
    }
    __syncthreads();

    const float ginv = 1.0f / fmaxf(sqrtf(g2[0] + g2[1]), 1e-12f);
    float* ob = out + (size_t)b * (NV_K * NV_C);
    #pragma unroll
    for (int i = 0; i < 8; i++) {
        int flat = i * 1024 + t;
        ob[flat] = vbuf[flat] * invrow[flat >> 7] * ginv;
    }
}

// ---------------------------------------------------------------------------
extern "C" void kernel_launch(void* const* d_in, const int* in_sizes, int n_in,
                              void* d_out, int out_size)
{
    const float* x         = (const float*)d_in[0];
    const float* conv_w    = (const float*)d_in[1];
    const float* centroids = (const float*)d_in[2];
    float* out = (float*)d_out;

    cudaFuncSetAttribute(netvlad_mma,
                         cudaFuncAttributeMaxDynamicSharedMemorySize, SMEM_TOTAL);
    netvlad_mma<<<NV_B * NV_SPLIT, 256, SMEM_TOTAL>>>(x, conv_w);
    netvlad_finalize<<<NV_B, 1024>>>(centroids, out);
}

// round 5
// speedup vs baseline: 2.2745x; 1.0051x over previous
#include <cuda_runtime.h>
#include <cuda_bf16.h>
#include <cstdint>

// NetVLAD: B=64, C=128, K=64, N=4096 — mma.sync bf16 3-term split + cp.async pipeline
#define NV_B 64
#define NV_C 128
#define NV_K 64
#define NV_N 4096
#define NV_SPLIT 8
#define NV_TILES 4

// smem pitches (bf16 elements)
#define PX 136      // Xn rows (c): 128 + 8 pad
#define PW 136      // W rows (k)
#define PA 72       // At rows (n): 64 + 8 pad

// smem byte offsets
#define XN_HI 0
#define XN_LO (XN_HI + 128 * PX * 2)      // 34816
#define W_HI  (XN_LO + 128 * PX * 2)      // 69632
#define W_LO  (W_HI + 64 * PW * 2)        // 87040
#define AT_HI (W_LO + 64 * PW * 2)        // 104448
#define AT_LO (AT_HI + 128 * PA * 2)      // 122880
#define ASUM_B (AT_LO + 128 * PA * 2)     // 141312
#define STG    (ASUM_B + 8 * 64 * 4)      // 143360 : fp32 staging [128][132]
#define STG_PITCH_B 528                   // 132 floats
#define SMEM_TOTAL (STG + 128 * STG_PITCH_B)   // 210944

// scratch partials
__device__ float g_pvlad[(size_t)NV_B * NV_SPLIT * NV_K * NV_C];  // 16 MB
__device__ float g_pasum[NV_B * NV_SPLIT * NV_K];

__device__ __forceinline__ uint32_t smem_u32(const void* p) {
    uint32_t a;
    asm("{ .reg .u64 t; cvta.to.shared.u64 t, %1; cvt.u32.u64 %0, t; }" : "=r"(a) : "l"(p));
    return a;
}
__device__ __forceinline__ void ldmx4(uint32_t* r, uint32_t a) {
    asm volatile("ldmatrix.sync.aligned.m8n8.x4.shared.b16 {%0,%1,%2,%3},[%4];"
        : "=r"(r[0]), "=r"(r[1]), "=r"(r[2]), "=r"(r[3]) : "r"(a));
}
__device__ __forceinline__ void ldmx4t(uint32_t* r, uint32_t a) {
    asm volatile("ldmatrix.sync.aligned.m8n8.x4.trans.shared.b16 {%0,%1,%2,%3},[%4];"
        : "=r"(r[0]), "=r"(r[1]), "=r"(r[2]), "=r"(r[3]) : "r"(a));
}
__device__ __forceinline__ void mma16816(float* d, const uint32_t* a, const uint32_t* b) {
    asm volatile("mma.sync.aligned.m16n8k16.row.col.f32.bf16.bf16.f32 "
        "{%0,%1,%2,%3},{%4,%5,%6,%7},{%8,%9},{%0,%1,%2,%3};"
        : "+f"(d[0]), "+f"(d[1]), "+f"(d[2]), "+f"(d[3])
        : "r"(a[0]), "r"(a[1]), "r"(a[2]), "r"(a[3]), "r"(b[0]), "r"(b[1]));
}
__device__ __forceinline__ void cpasync16(uint32_t dst, const void* src) {
    asm volatile("cp.async.cg.shared.global [%0],[%1],16;" :: "r"(dst), "l"(src));
}
#define CP_COMMIT() asm volatile("cp.async.commit_group;" ::: "memory")
#define CP_WAIT0()  asm volatile("cp.async.wait_group 0;" ::: "memory")

// ---------------------------------------------------------------------------
__global__ __launch_bounds__(256, 1)
void netvlad_mma(const float* __restrict__ x, const float* __restrict__ conv_w)
{
    extern __shared__ char smc[];
    const uint32_t sb = smem_u32(smc);
    const int tid  = threadIdx.x;
    const int w    = tid >> 5;
    const int lane = tid & 31;
    const int g    = lane >> 2;
    const int t4   = lane & 3;
    const int q    = lane >> 3;
    const int qi   = lane & 7;
    const int b    = blockIdx.x >> 3;
    const int s    = blockIdx.x & 7;

    const float* xb = x + (size_t)b * NV_C * NV_N + s * 512;

    // per-thread prefetch addressing: row = tid>>1, col16 = (tid&1)*16 + j
    const int pf_row  = tid >> 1;
    const int pf_col0 = (tid & 1) * 16;
    const uint32_t pf_dst = sb + STG + (uint32_t)pf_row * STG_PITCH_B + (uint32_t)pf_col0 * 16;
    const float* pf_src_base = xb + (size_t)pf_row * NV_N + pf_col0 * 4;

    // ---- prefetch tile 0 ----
    #pragma unroll
    for (int j = 0; j < 16; j++)
        cpasync16(pf_dst + 16u * j, pf_src_base + 4 * j);
    CP_COMMIT();

    // ---- W -> smem hi/lo (native [k][c] layout, padded pitch) ----
    {
        int k = tid >> 2, c0 = (tid & 3) * 32;
        const float* wr = conv_w + k * NV_C + c0;
        char* wh = smc + W_HI + k * (PW * 2) + c0 * 2;
        char* wl = smc + W_LO + k * (PW * 2) + c0 * 2;
        #pragma unroll
        for (int e = 0; e < 8; e++) {
            float4 v = *(const float4*)(wr + 4 * e);
            __nv_bfloat16 h0 = __float2bfloat16(v.x), h1 = __float2bfloat16(v.y);
            __nv_bfloat16 h2 = __float2bfloat16(v.z), h3 = __float2bfloat16(v.w);
            float l0 = v.x - __bfloat162float(h0), l1 = v.y - __bfloat162float(h1);
            float l2 = v.z - __bfloat162float(h2), l3 = v.w - __bfloat162float(h3);
            *(__nv_bfloat162*)(wh + 8 * e)     = __nv_bfloat162(h0, h1);
            *(__nv_bfloat162*)(wh + 8 * e + 4) = __nv_bfloat162(h2, h3);
            *(__nv_bfloat162*)(wl + 8 * e)     = __nv_bfloat162(__float2bfloat16(l0), __float2bfloat16(l1));
            *(__nv_bfloat162*)(wl + 8 * e + 4) = __nv_bfloat162(__float2bfloat16(l2), __float2bfloat16(l3));
        }
    }

    // ---- per-lane ldmatrix base addresses ----
    const uint32_t a1b = sb + XN_HI + (uint32_t)(((q >> 1) * 8 + qi) * (PX * 2))
                       + (uint32_t)((16 * w + (q & 1) * 8) * 2);
    const uint32_t b1b = sb + ((q & 2) ? W_LO : W_HI)
                       + (uint32_t)(qi * (PW * 2)) + (uint32_t)((q & 1) * 16);
    const uint32_t a2b = sb + XN_HI + (uint32_t)((16 * w + (q & 1) * 8 + qi) * (PX * 2))
                       + (uint32_t)(((q >> 1) * 8) * 2);
    const uint32_t b2b = sb + ((q & 2) ? AT_LO : AT_HI)
                       + (uint32_t)(((q & 1) * 8 + qi) * (PA * 2));

    float d2[8][4];
    float asum[8][2];
    #pragma unroll
    for (int kt = 0; kt < 8; kt++) {
        d2[kt][0] = d2[kt][1] = d2[kt][2] = d2[kt][3] = 0.f;
        asum[kt][0] = asum[kt][1] = 0.f;
    }

    for (int tt = 0; tt < NV_TILES; tt++) {
        CP_WAIT0();
        __syncthreads();   // STG holds tile tt; prior GEMM2 reads of Xn/At done

        // ---- convert staged x tile -> Xn hi/lo [c][n] (smem -> smem) ----
        {
            int cc = tid >> 1, nh = (tid & 1) * 64;
            const float* xr = (const float*)(smc + STG + cc * STG_PITCH_B) + nh;
            char* xnh = smc + XN_HI + cc * (PX * 2) + nh * 2;
            char* xnl = smc + XN_LO + cc * (PX * 2) + nh * 2;
            #pragma unroll
            for (int j = 0; j < 16; j++) {
                float4 v = *(const float4*)(xr + 4 * j);
                __nv_bfloat16 h0 = __float2bfloat16(v.x), h1 = __float2bfloat16(v.y);
                __nv_bfloat16 h2 = __float2bfloat16(v.z), h3 = __float2bfloat16(v.w);
                float l0 = v.x - __bfloat162float(h0), l1 = v.y - __bfloat162float(h1);
                float l2 = v.z - __bfloat162float(h2), l3 = v.w - __bfloat162float(h3);
                *(__nv_bfloat162*)(xnh + 8 * j)     = __nv_bfloat162(h0, h1);
                *(__nv_bfloat162*)(xnh + 8 * j + 4) = __nv_bfloat162(h2, h3);
                *(__nv_bfloat162*)(xnl + 8 * j)     = __nv_bfloat162(__float2bfloat16(l0), __float2bfloat16(l1));
                *(__nv_bfloat162*)(xnl + 8 * j + 4) = __nv_bfloat162(__float2bfloat16(l2), __float2bfloat16(l3));
            }
        }
        __syncthreads();   // Xn ready; STG free for next prefetch

        // ---- prefetch tile tt+1 while GEMMs run ----
        if (tt + 1 < NV_TILES) {
            const float* src = pf_src_base + (tt + 1) * 128;
            #pragma unroll
            for (int j = 0; j < 16; j++)
                cpasync16(pf_dst + 16u * j, src + 4 * j);
            CP_COMMIT();
        }

        // ---- GEMM1: L[n(16w..+16)][k(64)] = Xt @ W^T, 3-term split ----
        float d1[8][4];
        #pragma unroll
        for (int kt = 0; kt < 8; kt++)
            d1[kt][0] = d1[kt][1] = d1[kt][2] = d1[kt][3] = 0.f;

        #pragma unroll
        for (int cs = 0; cs < 8; cs++) {
            uint32_t ah[4], al[4];
            ldmx4t(ah, a1b + cs * 16 * (PX * 2));
            ldmx4t(al, a1b + cs * 16 * (PX * 2) + (XN_LO - XN_HI));
            #pragma unroll
            for (int kt = 0; kt < 8; kt++) {
                uint32_t bb[4];
                ldmx4(bb, b1b + kt * (8 * PW * 2) + cs * 32);
                mma16816(d1[kt], ah, bb);
                mma16816(d1[kt], ah, bb + 2);
                mma16816(d1[kt], al, bb);
            }
        }

        // ---- softmax over k, in registers ----
        {
            float m0 = -1e30f, m1 = -1e30f;
            #pragma unroll
            for (int kt = 0; kt < 8; kt++) {
                m0 = fmaxf(m0, fmaxf(d1[kt][0], d1[kt][1]));
                m1 = fmaxf(m1, fmaxf(d1[kt][2], d1[kt][3]));
            }
            m0 = fmaxf(m0, __shfl_xor_sync(0xffffffffu, m0, 1));
            m0 = fmaxf(m0, __shfl_xor_sync(0xffffffffu, m0, 2));
            m1 = fmaxf(m1, __shfl_xor_sync(0xffffffffu, m1, 1));
            m1 = fmaxf(m1, __shfl_xor_sync(0xffffffffu, m1, 2));
            float s0 = 0.f, s1 = 0.f;
            #pragma unroll
            for (int kt = 0; kt < 8; kt++) {
                d1[kt][0] = __expf(d1[kt][0] - m0); s0 += d1[kt][0];
                d1[kt][1] = __expf(d1[kt][1] - m0); s0 += d1[kt][1];
                d1[kt][2] = __expf(d1[kt][2] - m1); s1 += d1[kt][2];
                d1[kt][3] = __expf(d1[kt][3] - m1); s1 += d1[kt][3];
            }
            s0 += __shfl_xor_sync(0xffffffffu, s0, 1);
            s0 += __shfl_xor_sync(0xffffffffu, s0, 2);
            s1 += __shfl_xor_sync(0xffffffffu, s1, 1);
            s1 += __shfl_xor_sync(0xffffffffu, s1, 2);
            float inv0 = 1.0f / s0, inv1 = 1.0f / s1;

            char* r0h = smc + AT_HI + (16 * w + g) * (PA * 2) + (2 * t4) * 2;
            char* r1h = r0h + 8 * (PA * 2);
            #pragma unroll
            for (int kt = 0; kt < 8; kt++) {
                float a00 = d1[kt][0] * inv0, a01 = d1[kt][1] * inv0;
                float a10 = d1[kt][2] * inv1, a11 = d1[kt][3] * inv1;
                asum[kt][0] += a00 + a10;
                asum[kt][1] += a01 + a11;
                __nv_bfloat16 h00 = __float2bfloat16(a00), h01 = __float2bfloat16(a01);
                __nv_bfloat16 h10 = __float2bfloat16(a10), h11 = __float2bfloat16(a11);
                float e00 = a00 - __bfloat162float(h00), e01 = a01 - __bfloat162float(h01);
                float e10 = a10 - __bfloat162float(h10), e11 = a11 - __bfloat162float(h11);
                *(__nv_bfloat162*)(r0h + kt * 16) = __nv_bfloat162(h00, h01);
                *(__nv_bfloat162*)(r1h + kt * 16) = __nv_bfloat162(h10, h11);
                *(__nv_bfloat162*)(r0h + kt * 16 + (AT_LO - AT_HI)) =
                    __nv_bfloat162(__float2bfloat16(e00), __float2bfloat16(e01));
                *(__nv_bfloat162*)(r1h + kt * 16 + (AT_LO - AT_HI)) =
                    __nv_bfloat162(__float2bfloat16(e10), __float2bfloat16(e11));
            }
        }
        __syncthreads();   // At ready

        // ---- GEMM2: V[c(16w..+16)][k(64)] += Xn @ At^T, 3-term split ----
        #pragma unroll
        for (int ns = 0; ns < 8; ns++) {
            uint32_t ah[4], al[4];
            ldmx4(ah, a2b + ns * 32);
            ldmx4(al, a2b + ns * 32 + (XN_LO - XN_HI));
            #pragma unroll
            for (int kt = 0; kt < 8; kt++) {
                uint32_t bb[4];
                ldmx4t(bb, b2b + ns * 16 * (PA * 2) + kt * 16);
                mma16816(d2[kt], ah, bb);
                mma16816(d2[kt], ah, bb + 2);
                mma16816(d2[kt], al, bb);
            }
        }
        // no trailing sync: loop-top sync covers next conversion's WAR hazard
    }

    __syncthreads();

    // ---- stage D2 into STG as [k][c] fp32, then coalesced drain ----
    {
        float* dstg = (float*)(smc + STG);
        const int c0 = 16 * w + g;
        #pragma unroll
        for (int kt = 0; kt < 8; kt++) {
            int k0 = kt * 8 + 2 * t4;
            dstg[k0 * NV_C + c0]           = d2[kt][0];
            dstg[(k0 + 1) * NV_C + c0]     = d2[kt][1];
            dstg[k0 * NV_C + c0 + 8]       = d2[kt][2];
            dstg[(k0 + 1) * NV_C + c0 + 8] = d2[kt][3];
        }
        __syncthreads();
        float4* pv4 = (float4*)(g_pvlad + (size_t)blockIdx.x * (NV_K * NV_C));
        const float4* sg4 = (const float4*)dstg;
        #pragma unroll
        for (int i = 0; i < 8; i++)
            pv4[i * 256 + tid] = sg4[i * 256 + tid];
    }

    // ---- asum reduce ----
    float* asum_buf = (float*)(smc + ASUM_B);
    #pragma unroll
    for (int kt = 0; kt < 8; kt++) {
        #pragma unroll
        for (int j = 0; j < 2; j++) {
            float v = asum[kt][j];
            v += __shfl_xor_sync(0xffffffffu, v, 4);
            v += __shfl_xor_sync(0xffffffffu, v, 8);
            v += __shfl_xor_sync(0xffffffffu, v, 16);
            asum[kt][j] = v;
        }
    }
    if (lane < 4) {
        #pragma unroll
        for (int kt = 0; kt < 8; kt++) {
            asum_buf[w * 64 + kt * 8 + 2 * t4]     = asum[kt][0];
            asum_buf[w * 64 + kt * 8 + 2 * t4 + 1] = asum[kt][1];
        }
    }
    __syncthreads();
    if (tid < 64) {
        float ssum = 0.f;
        #pragma unroll
        for (int ww = 0; ww < 8; ww++) ssum += asum_buf[ww * 64 + tid];
        g_pasum[blockIdx.x * NV_K + tid] = ssum;
    }
}

// ---------------------------------------------------------------------------
// finalize: reduce splits, subtract asum*centroid, intra + global L2 normalize
// ---------------------------------------------------------------------------
__global__ __launch_bounds__(1024)
void netvlad_finalize(const float* __restrict__ centroids, float* __restrict__ out)
{
    __shared__ float vbuf[NV_K * NV_C];
    __shared__ float wpart[NV_K][4];
    __shared__ float asumt[NV_K];
    __shared__ float invrow[NV_K];
    __shared__ float g2[2];

    const int b = blockIdx.x, t = threadIdx.x;
    const int w = t >> 5, lane = t & 31;

    if (t < NV_K) {
        float sum = 0.f;
        #pragma unroll
        for (int sp = 0; sp < NV_SPLIT; sp++)
            sum += g_pasum[(b * NV_SPLIT + sp) * NV_K + t];
        asumt[t] = sum;
    }
    __syncthreads();

    const size_t base = (size_t)b * NV_SPLIT * (NV_K * NV_C);
    #pragma unroll
    for (int i = 0; i < 8; i++) {
        int flat = i * 1024 + t;
        int k = flat >> 7;
        float v = 0.f;
        #pragma unroll
        for (int sp = 0; sp < NV_SPLIT; sp++)
            v += g_pvlad[base + (size_t)sp * (NV_K * NV_C) + flat];
        v -= asumt[k] * centroids[flat];
        vbuf[flat] = v;
        float v2 = v * v;
        #pragma unroll
        for (int o = 16; o > 0; o >>= 1)
            v2 += __shfl_xor_sync(0xffffffffu, v2, o);
        if (lane == 0) wpart[k][w & 3] = v2;
    }
    __syncthreads();

    if (t < NV_K) {
        float rs  = wpart[t][0] + wpart[t][1] + wpart[t][2] + wpart[t][3];
        float rn  = sqrtf(rs);
        float inv = 1.0f / fmaxf(rn, 1e-12f);
        invrow[t] = inv;
        float c1 = rn * inv;
        float contrib = c1 * c1;
        #pragma unroll
        for (int o = 16; o > 0; o >>= 1)
            contrib += __shfl_xor_sync(0xffffffffu, contrib, o);
        if (lane == 0) g2[w] = contrib;
    }
    __syncthreads();

    const float ginv = 1.0f / fmaxf(sqrtf(g2[0] + g2[1]), 1e-12f);
    float* ob = out + (size_t)b * (NV_K * NV_C);
    #pragma unroll
    for (int i = 0; i < 8; i++) {
        int flat = i * 1024 + t;
        ob[flat] = vbuf[flat] * invrow[flat >> 7] * ginv;
    }
}

// ---------------------------------------------------------------------------
extern "C" void kernel_launch(void* const* d_in, const int* in_sizes, int n_in,
                              void* d_out, int out_size)
{
    const float* x         = (const float*)d_in[0];
    const float* conv_w    = (const float*)d_in[1];
    const float* centroids = (const float*)d_in[2];
    float* out = (float*)d_out;

    cudaFuncSetAttribute(netvlad_mma,
                         cudaFuncAttributeMaxDynamicSharedMemorySize, SMEM_TOTAL);
    netvlad_mma<<<NV_B * NV_SPLIT, 256, SMEM_TOTAL>>>(x, conv_w);
    netvlad_finalize<<<NV_B, 1024>>>(centroids, out);
}